// round 1
// baseline (speedup 1.0000x reference)
#include <cuda_runtime.h>
#include <cuda_bf16.h>
#include <cstdint>

#define DIM 128
#define N_NODES_MAX 50000
#define TILE_ROWS 64

// Scratch for the SpMM accumulator (allocation-free rule: __device__ global).
__device__ float g_side[(size_t)N_NODES_MAX * DIM];

// ---------------------------------------------------------------------------
// Kernel 1: zero the scratch accumulator
// ---------------------------------------------------------------------------
__global__ void zero_kernel(int n4) {
    int i = blockIdx.x * blockDim.x + threadIdx.x;
    float4* p = reinterpret_cast<float4*>(g_side);
    if (i < n4) p[i] = make_float4(0.f, 0.f, 0.f, 0.f);
}

// ---------------------------------------------------------------------------
// Kernel 2: COO scatter:  side[rows[e], :] += vals[e] * ego[cols[e], :]
// One warp per edge; each lane handles one float4 (32 lanes * 4 = 128).
// Vector reduction (red.global.add.v4.f32) to cut L2 atomic op count 4x.
// ---------------------------------------------------------------------------
__global__ void scatter_kernel(const float* __restrict__ ego,
                               const float* __restrict__ vals,
                               const int*   __restrict__ rows,
                               const int*   __restrict__ cols,
                               int E) {
    int gw = (blockIdx.x * blockDim.x + threadIdx.x) >> 5;
    if (gw >= E) return;
    int lane = threadIdx.x & 31;

    int   c = __ldg(&cols[gw]);
    int   r = __ldg(&rows[gw]);
    float v = __ldg(&vals[gw]);

    float4 x = reinterpret_cast<const float4*>(ego + (size_t)c * DIM)[lane];
    float* dst = g_side + (size_t)r * DIM + lane * 4;
    asm volatile("red.global.add.v4.f32 [%0], {%1,%2,%3,%4};"
                 :: "l"(dst), "f"(v * x.x), "f"(v * x.y), "f"(v * x.z), "f"(v * x.w)
                 : "memory");
}

// ---------------------------------------------------------------------------
// Kernel 3: fused dense part
//   side_r = bf16_round(side)
//   out = lrelu((ego+side_r) @ W1^T + b1) + lrelu((ego*side_r) @ W2^T + b2)
//
// Persistent blocks (grid = #SMs), W1^T/W2^T staged once per block in smem
// (stride 132 floats: keeps float4 alignment + conflict-free LDS.128).
// Each tile = 64 rows; warp computes 8 rows x 128 cols (4 cols/lane),
// 64 fp32 accumulators per thread.
// ---------------------------------------------------------------------------
#define WT_STRIDE 132
#define SMEM_FLOATS (2 * DIM * WT_STRIDE + 2 * TILE_ROWS * DIM)
#define SMEM_BYTES  (SMEM_FLOATS * 4)

__global__ void __launch_bounds__(256, 1)
dense_kernel(const float* __restrict__ ego,
             const float* __restrict__ W1, const float* __restrict__ b1,
             const float* __restrict__ W2, const float* __restrict__ b2,
             float* __restrict__ out, int n) {
    extern __shared__ float smem[];
    float* Wt1 = smem;                       // [128][132]  Wt1[k][o] = W1[o][k]
    float* Wt2 = Wt1 + DIM * WT_STRIDE;      // [128][132]
    float* s_t = Wt2 + DIM * WT_STRIDE;      // [64][128]
    float* p_t = s_t + TILE_ROWS * DIM;      // [64][128]

    int tid  = threadIdx.x;
    int warp = tid >> 5;
    int lane = tid & 31;

    // Stage transposed weights. Consecutive tid -> consecutive o: STS
    // conflict-free; LDG is strided (W is only 64KB, L2-resident, one-time).
    for (int i = tid; i < DIM * DIM; i += 256) {
        int o = i & (DIM - 1);
        int k = i >> 7;
        Wt1[k * WT_STRIDE + o] = __ldg(&W1[o * DIM + k]);
        Wt2[k * WT_STRIDE + o] = __ldg(&W2[o * DIM + k]);
    }
    float4 b1v = reinterpret_cast<const float4*>(b1)[lane];
    float4 b2v = reinterpret_cast<const float4*>(b2)[lane];
    __syncthreads();

    int numTiles = (n + TILE_ROWS - 1) / TILE_ROWS;
    const float4* ego4  = reinterpret_cast<const float4*>(ego);
    const float4* side4 = reinterpret_cast<const float4*>(g_side);
    float4* out4 = reinterpret_cast<float4*>(out);

    for (int tile = blockIdx.x; tile < numTiles; tile += gridDim.x) {
        int row0 = tile * TILE_ROWS;

        // ---- fill s/p tile (float4 granularity: 64 rows * 32 float4) ----
        for (int i = tid; i < TILE_ROWS * (DIM / 4); i += 256) {
            int r   = i >> 5;
            int c   = i & 31;
            int row = row0 + r;
            float4 e = make_float4(0.f, 0.f, 0.f, 0.f);
            float4 d = e;
            if (row < n) {
                e = ego4[(size_t)row * 32 + c];
                d = side4[(size_t)row * 32 + c];
            }
            // bf16 round-trip (matches reference astype(bf16).astype(f32))
            d.x = __bfloat162float(__float2bfloat16(d.x));
            d.y = __bfloat162float(__float2bfloat16(d.y));
            d.z = __bfloat162float(__float2bfloat16(d.z));
            d.w = __bfloat162float(__float2bfloat16(d.w));
            float4 s = make_float4(e.x + d.x, e.y + d.y, e.z + d.z, e.w + d.w);
            float4 p = make_float4(e.x * d.x, e.y * d.y, e.z * d.z, e.w * d.w);
            reinterpret_cast<float4*>(s_t)[i] = s;
            reinterpret_cast<float4*>(p_t)[i] = p;
        }
        __syncthreads();

        // ---- compute: warp handles rows [warp*8, warp*8+8) of the tile ----
        float acc1[8][4];
        float acc2[8][4];
        #pragma unroll
        for (int r = 0; r < 8; r++)
            #pragma unroll
            for (int j = 0; j < 4; j++) { acc1[r][j] = 0.f; acc2[r][j] = 0.f; }

        const float* srow = s_t + (warp * 8) * DIM;
        const float* prow = p_t + (warp * 8) * DIM;

        #pragma unroll 4
        for (int k = 0; k < DIM; k++) {
            float4 w1 = *reinterpret_cast<const float4*>(Wt1 + k * WT_STRIDE + lane * 4);
            float4 w2 = *reinterpret_cast<const float4*>(Wt2 + k * WT_STRIDE + lane * 4);
            #pragma unroll
            for (int r = 0; r < 8; r++) {
                float s = srow[r * DIM + k];
                float p = prow[r * DIM + k];
                acc1[r][0] += s * w1.x; acc1[r][1] += s * w1.y;
                acc1[r][2] += s * w1.z; acc1[r][3] += s * w1.w;
                acc2[r][0] += p * w2.x; acc2[r][1] += p * w2.y;
                acc2[r][2] += p * w2.z; acc2[r][3] += p * w2.w;
            }
        }

        // ---- epilogue: bias + leaky_relu(0.01) + sum, store ----
        #pragma unroll
        for (int r = 0; r < 8; r++) {
            int row = row0 + warp * 8 + r;
            if (row < n) {
                float4 o;
                float v1, v2;
                v1 = acc1[r][0] + b1v.x; v1 = v1 > 0.f ? v1 : 0.01f * v1;
                v2 = acc2[r][0] + b2v.x; v2 = v2 > 0.f ? v2 : 0.01f * v2;
                o.x = v1 + v2;
                v1 = acc1[r][1] + b1v.y; v1 = v1 > 0.f ? v1 : 0.01f * v1;
                v2 = acc2[r][1] + b2v.y; v2 = v2 > 0.f ? v2 : 0.01f * v2;
                o.y = v1 + v2;
                v1 = acc1[r][2] + b1v.z; v1 = v1 > 0.f ? v1 : 0.01f * v1;
                v2 = acc2[r][2] + b2v.z; v2 = v2 > 0.f ? v2 : 0.01f * v2;
                o.z = v1 + v2;
                v1 = acc1[r][3] + b1v.w; v1 = v1 > 0.f ? v1 : 0.01f * v1;
                v2 = acc2[r][3] + b2v.w; v2 = v2 > 0.f ? v2 : 0.01f * v2;
                o.w = v1 + v2;
                out4[(size_t)row * 32 + lane] = o;
            }
        }
        __syncthreads();
    }
}

// ---------------------------------------------------------------------------
extern "C" void kernel_launch(void* const* d_in, const int* in_sizes, int n_in,
                              void* d_out, int out_size) {
    const float* ego  = (const float*)d_in[0];
    const float* vals = (const float*)d_in[1];
    const float* W1   = (const float*)d_in[2];
    const float* b1   = (const float*)d_in[3];
    const float* W2   = (const float*)d_in[4];
    const float* b2   = (const float*)d_in[5];
    const int*   rows = (const int*)d_in[6];
    const int*   cols = (const int*)d_in[7];
    float*       out  = (float*)d_out;

    int n = in_sizes[0] / DIM;   // 50000
    int E = in_sizes[1];         // 640000

    cudaFuncSetAttribute(dense_kernel,
                         cudaFuncAttributeMaxDynamicSharedMemorySize, SMEM_BYTES);

    // 1) zero scratch
    int n4 = n * (DIM / 4);
    zero_kernel<<<(n4 + 255) / 256, 256>>>(n4);

    // 2) edge scatter (one warp per edge, 8 warps/block)
    int blocks = (E + 7) / 8;
    scatter_kernel<<<blocks, 256>>>(ego, vals, rows, cols, E);

    // 3) fused dense
    dense_kernel<<<148, 256, SMEM_BYTES>>>(ego, W1, b1, W2, b2, out, n);
}

// round 2
// speedup vs baseline: 1.0306x; 1.0306x over previous
#include <cuda_runtime.h>
#include <cuda_bf16.h>
#include <cstdint>

#define DIM 128
#define N_NODES_MAX 50000
#define TILE_ROWS 64

// Scratch for the SpMM accumulator (allocation-free rule: __device__ global).
__device__ float g_side[(size_t)N_NODES_MAX * DIM];

// ---------------------------------------------------------------------------
// packed f32x2 helpers (Blackwell: 2x fp32 FMA throughput, PTX-only)
// ---------------------------------------------------------------------------
__device__ __forceinline__ unsigned long long pack2(float a, float b) {
    unsigned long long r;
    asm("mov.b64 %0, {%1, %2};" : "=l"(r) : "f"(a), "f"(b));
    return r;
}
__device__ __forceinline__ void ffma2(unsigned long long& d,
                                      unsigned long long a,
                                      unsigned long long b) {
    asm("fma.rn.f32x2 %0, %1, %2, %3;" : "=l"(d) : "l"(a), "l"(b), "l"(d));
}
__device__ __forceinline__ float2 unpack2(unsigned long long v) {
    float2 r;
    asm("mov.b64 {%0, %1}, %2;" : "=f"(r.x), "=f"(r.y) : "l"(v));
    return r;
}

// ---------------------------------------------------------------------------
// Kernel: COO scatter:  side[rows[e], :] += vals[e] * ego[cols[e], :]
// One warp per edge; each lane handles one float4 (32 lanes * 4 = 128).
// Vector reduction (red.global.add.v4.f32) to cut L2 atomic op count 4x.
// ---------------------------------------------------------------------------
__global__ void scatter_kernel(const float* __restrict__ ego,
                               const float* __restrict__ vals,
                               const int*   __restrict__ rows,
                               const int*   __restrict__ cols,
                               int E) {
    int gw = (blockIdx.x * blockDim.x + threadIdx.x) >> 5;
    if (gw >= E) return;
    int lane = threadIdx.x & 31;

    int   c = __ldg(&cols[gw]);
    int   r = __ldg(&rows[gw]);
    float v = __ldg(&vals[gw]);

    float4 x = reinterpret_cast<const float4*>(ego + (size_t)c * DIM)[lane];
    float* dst = g_side + (size_t)r * DIM + lane * 4;
    asm volatile("red.global.add.v4.f32 [%0], {%1,%2,%3,%4};"
                 :: "l"(dst), "f"(v * x.x), "f"(v * x.y), "f"(v * x.z), "f"(v * x.w)
                 : "memory");
}

// ---------------------------------------------------------------------------
// Kernel: fused dense part, f32x2 packed FMA inner loop
//   side_r = bf16_round(side)
//   out = lrelu((ego+side_r) @ W1^T + b1) + lrelu((ego*side_r) @ W2^T + b2)
// ---------------------------------------------------------------------------
#define WT_STRIDE 132
#define SMEM_FLOATS (2 * DIM * WT_STRIDE + 2 * TILE_ROWS * DIM)
#define SMEM_BYTES  (SMEM_FLOATS * 4)

__global__ void __launch_bounds__(256, 1)
dense_kernel(const float* __restrict__ ego,
             const float* __restrict__ W1, const float* __restrict__ b1,
             const float* __restrict__ W2, const float* __restrict__ b2,
             float* __restrict__ out, int n) {
    extern __shared__ float smem[];
    float* Wt1 = smem;                       // [128][132]  Wt1[k][o] = W1[o][k]
    float* Wt2 = Wt1 + DIM * WT_STRIDE;      // [128][132]
    float* s_t = Wt2 + DIM * WT_STRIDE;      // [64][128]
    float* p_t = s_t + TILE_ROWS * DIM;      // [64][128]

    int tid  = threadIdx.x;
    int warp = tid >> 5;
    int lane = tid & 31;

    // Stage transposed weights (one-time; W is L2-resident).
    for (int i = tid; i < DIM * DIM; i += 256) {
        int o = i & (DIM - 1);
        int k = i >> 7;
        Wt1[k * WT_STRIDE + o] = __ldg(&W1[o * DIM + k]);
        Wt2[k * WT_STRIDE + o] = __ldg(&W2[o * DIM + k]);
    }
    float4 b1v = reinterpret_cast<const float4*>(b1)[lane];
    float4 b2v = reinterpret_cast<const float4*>(b2)[lane];
    __syncthreads();

    int numTiles = (n + TILE_ROWS - 1) / TILE_ROWS;
    const float4* ego4  = reinterpret_cast<const float4*>(ego);
    const float4* side4 = reinterpret_cast<const float4*>(g_side);
    float4* out4 = reinterpret_cast<float4*>(out);

    for (int tile = blockIdx.x; tile < numTiles; tile += gridDim.x) {
        int row0 = tile * TILE_ROWS;

        // ---- fill s/p tile ----
        for (int i = tid; i < TILE_ROWS * (DIM / 4); i += 256) {
            int r   = i >> 5;
            int c   = i & 31;
            int row = row0 + r;
            float4 e = make_float4(0.f, 0.f, 0.f, 0.f);
            float4 d = e;
            if (row < n) {
                e = ego4[(size_t)row * 32 + c];
                d = side4[(size_t)row * 32 + c];
            }
            // bf16 round-trip (matches reference astype(bf16).astype(f32))
            d.x = __bfloat162float(__float2bfloat16(d.x));
            d.y = __bfloat162float(__float2bfloat16(d.y));
            d.z = __bfloat162float(__float2bfloat16(d.z));
            d.w = __bfloat162float(__float2bfloat16(d.w));
            float4 s = make_float4(e.x + d.x, e.y + d.y, e.z + d.z, e.w + d.w);
            float4 p = make_float4(e.x * d.x, e.y * d.y, e.z * d.z, e.w * d.w);
            reinterpret_cast<float4*>(s_t)[i] = s;
            reinterpret_cast<float4*>(p_t)[i] = p;
        }
        __syncthreads();

        // ---- compute: warp handles rows [warp*8, warp*8+8) of the tile ----
        // Accumulators: per row, 4 output cols as 2 packed f32x2.
        unsigned long long acc1[8][2];
        unsigned long long acc2[8][2];
        #pragma unroll
        for (int r = 0; r < 8; r++) {
            acc1[r][0] = 0ull; acc1[r][1] = 0ull;
            acc2[r][0] = 0ull; acc2[r][1] = 0ull;
        }

        const float* srow = s_t + (warp * 8) * DIM;
        const float* prow = p_t + (warp * 8) * DIM;

        for (int k0 = 0; k0 < DIM; k0 += 4) {
            ulonglong2 w1v[4], w2v[4];
            #pragma unroll
            for (int kk = 0; kk < 4; kk++) {
                w1v[kk] = *reinterpret_cast<const ulonglong2*>(
                              Wt1 + (k0 + kk) * WT_STRIDE + lane * 4);
                w2v[kk] = *reinterpret_cast<const ulonglong2*>(
                              Wt2 + (k0 + kk) * WT_STRIDE + lane * 4);
            }
            #pragma unroll
            for (int r = 0; r < 8; r++) {
                float4 sv = *reinterpret_cast<const float4*>(srow + r * DIM + k0);
                float4 pv = *reinterpret_cast<const float4*>(prow + r * DIM + k0);
                unsigned long long sb, pb;

                sb = pack2(sv.x, sv.x);
                ffma2(acc1[r][0], sb, w1v[0].x); ffma2(acc1[r][1], sb, w1v[0].y);
                pb = pack2(pv.x, pv.x);
                ffma2(acc2[r][0], pb, w2v[0].x); ffma2(acc2[r][1], pb, w2v[0].y);

                sb = pack2(sv.y, sv.y);
                ffma2(acc1[r][0], sb, w1v[1].x); ffma2(acc1[r][1], sb, w1v[1].y);
                pb = pack2(pv.y, pv.y);
                ffma2(acc2[r][0], pb, w2v[1].x); ffma2(acc2[r][1], pb, w2v[1].y);

                sb = pack2(sv.z, sv.z);
                ffma2(acc1[r][0], sb, w1v[2].x); ffma2(acc1[r][1], sb, w1v[2].y);
                pb = pack2(pv.z, pv.z);
                ffma2(acc2[r][0], pb, w2v[2].x); ffma2(acc2[r][1], pb, w2v[2].y);

                sb = pack2(sv.w, sv.w);
                ffma2(acc1[r][0], sb, w1v[3].x); ffma2(acc1[r][1], sb, w1v[3].y);
                pb = pack2(pv.w, pv.w);
                ffma2(acc2[r][0], pb, w2v[3].x); ffma2(acc2[r][1], pb, w2v[3].y);
            }
        }

        // ---- epilogue: bias + leaky_relu(0.01) + sum, store ----
        #pragma unroll
        for (int r = 0; r < 8; r++) {
            int row = row0 + warp * 8 + r;
            if (row < n) {
                float2 a1lo = unpack2(acc1[r][0]);
                float2 a1hi = unpack2(acc1[r][1]);
                float2 a2lo = unpack2(acc2[r][0]);
                float2 a2hi = unpack2(acc2[r][1]);
                float4 o;
                float v1, v2;
                v1 = a1lo.x + b1v.x; v1 = v1 > 0.f ? v1 : 0.01f * v1;
                v2 = a2lo.x + b2v.x; v2 = v2 > 0.f ? v2 : 0.01f * v2;
                o.x = v1 + v2;
                v1 = a1lo.y + b1v.y; v1 = v1 > 0.f ? v1 : 0.01f * v1;
                v2 = a2lo.y + b2v.y; v2 = v2 > 0.f ? v2 : 0.01f * v2;
                o.y = v1 + v2;
                v1 = a1hi.x + b1v.z; v1 = v1 > 0.f ? v1 : 0.01f * v1;
                v2 = a2hi.x + b2v.z; v2 = v2 > 0.f ? v2 : 0.01f * v2;
                o.z = v1 + v2;
                v1 = a1hi.y + b1v.w; v1 = v1 > 0.f ? v1 : 0.01f * v1;
                v2 = a2hi.y + b2v.w; v2 = v2 > 0.f ? v2 : 0.01f * v2;
                o.w = v1 + v2;
                out4[(size_t)row * 32 + lane] = o;
            }
        }
        __syncthreads();
    }
}

// ---------------------------------------------------------------------------
extern "C" void kernel_launch(void* const* d_in, const int* in_sizes, int n_in,
                              void* d_out, int out_size) {
    const float* ego  = (const float*)d_in[0];
    const float* vals = (const float*)d_in[1];
    const float* W1   = (const float*)d_in[2];
    const float* b1   = (const float*)d_in[3];
    const float* W2   = (const float*)d_in[4];
    const float* b2   = (const float*)d_in[5];
    const int*   rows = (const int*)d_in[6];
    const int*   cols = (const int*)d_in[7];
    float*       out  = (float*)d_out;

    int n = in_sizes[0] / DIM;   // 50000
    int E = in_sizes[1];         // 640000

    cudaFuncSetAttribute(dense_kernel,
                         cudaFuncAttributeMaxDynamicSharedMemorySize, SMEM_BYTES);

    // 1) zero scratch (async memset: graph-capturable, no alloc)
    void* side_ptr = nullptr;
    cudaGetSymbolAddress(&side_ptr, g_side);
    cudaMemsetAsync(side_ptr, 0, (size_t)n * DIM * sizeof(float));

    // 2) edge scatter (one warp per edge, 8 warps/block)
    int blocks = (E + 7) / 8;
    scatter_kernel<<<blocks, 256>>>(ego, vals, rows, cols, E);

    // 3) fused dense
    dense_kernel<<<148, 256, SMEM_BYTES>>>(ego, W1, b1, W2, b2, out, n);
}